// round 12
// baseline (speedup 1.0000x reference)
#include <cuda_runtime.h>
#include <cstdint>

// DiscreteAutoregressiveFlow: exact one-hot algebra over Z_257.
// next = (x_t * m[p] + c[p]) mod 257, per-state (m,c) from argmax of W[p]+b.
// Round 12: ONE fused kernel. 33 table blocks + 1024 work blocks. Each work
// block owns 64 rows: streams them (extract x -> smem, zero out), runs its
// 4 segment-maps (258 entries x 16 steps), composes a block-map, cooperative
// per-batch stitch (16 blocks), replays + scatters. Streaming and chain ALU
// share the same blocks -> chains hide under the 134MB memory stream.

#define V        257
#define B        64
#define L        1024
#define SEGLEN   16
#define UNITS    4                        // segments per work block
#define ROWS_PB  (UNITS * SEGLEN)         // 64 rows per block
#define BPB      (L / ROWS_PB)            // 16 blocks per batch
#define WBLK     (B * BPB)                // 1024 work blocks
#define TBLK     33                       // table blocks (264 warps >= 258)
#define REP      8                        // table replication factor
#define NST      258                      // states 0..256 plus 257 = ZERO
#define RU4      ((ROWS_PB * V) / 4)      // 4112 uint4 per block region
#define DEADE    (66048u << 9)            // dead: m=0, c=66048 -> slot 0

// Slot convention: slot 0 = ZERO/dead; slot s in [1,513] = state (s-1) mod 257.
// Step: z = x*m + c (alive z <= 65792); z mod 257 == (z&255)-(z>>8) (mod 257);
// w = lo - hi + 258 in [1,513] alive, 0 for the dead trap (hi=258). Branch-free.

__device__ unsigned g_tab[NST];                          // m | c<<9 (or DEADE)
__device__ __align__(16) short g_bmap[B * BPB * NST];    // per-block maps
__device__ int g_entry[B * BPB];                         // entry state per block
__device__ int g_done[B];                                // all zero-init,
__device__ volatile int g_go[B];                         // self-resetting
__device__ int g_fin[B];
__device__ int g_tabdone;
__device__ int g_allfin;

__device__ __forceinline__ int slot2state(int s) {       // [0,513] -> 0..257
    return (s == 0) ? V : ((s <= V) ? s - 1 : s - (V + 1));
}

__global__ void __launch_bounds__(256) k_F(const float* __restrict__ W,
                                           const float* __restrict__ bb,
                                           const int*   __restrict__ inv_table,
                                           const uint4* __restrict__ x4,
                                           uint4*       __restrict__ out4) {
    __shared__ unsigned tabR[514 * REP];                 // 16448 B
    __shared__ __align__(16) short segmapS[UNITS * NST]; // 2064 B
    __shared__ __align__(16) short bmapsS[BPB * NST];    // 8256 B (stitch)
    __shared__ __align__(16) int   sxs[SEGLEN * UNITS];  // [t*4 + u]
    __shared__ int entryU[UNITS];
    __shared__ int isLast;

    int bid = blockIdx.x;
    int tid = threadIdx.x;

    // ---------------- role: per-state tables (first 33 blocks) --------------
    if (bid < TBLK) {
        int p    = bid * 8 + (tid >> 5);
        int lane = tid & 31;
        if (p < NST) {
            const float* wrow = (p < V) ? (W + (size_t)p * (2 * V)) : nullptr;
            int bestj[2];
            #pragma unroll
            for (int h = 0; h < 2; h++) {
                float bv = -3.402823466e38f;
                int   bj = 0;
                for (int j = lane; j < V; j += 32) {
                    int   col = h * V + j;
                    float v   = bb[col] + (wrow ? wrow[col] : 0.0f);
                    if (v > bv) { bv = v; bj = j; }      // first-max == jnp.argmax
                }
                #pragma unroll
                for (int off = 16; off; off >>= 1) {
                    float ov = __shfl_down_sync(0xffffffffu, bv, off);
                    int   oj = __shfl_down_sync(0xffffffffu, bj, off);
                    if (ov > bv || (ov == bv && oj < bj)) { bv = ov; bj = oj; }
                }
                bestj[h] = bj;
            }
            if (lane == 0) {
                int l = bestj[0], s = bestj[1];
                int m = inv_table[s];                    // 0 iff s==0
                unsigned e = DEADE;
                if (m != 0) {
                    int c = (V - (l * m) % V) % V;
                    e = (unsigned)m | ((unsigned)c << 9);
                }
                g_tab[p] = e;
            }
        }
        __threadfence();
        __syncthreads();
        if (tid == 0) atomicAdd(&g_tabdone, 1);
        return;
    }

    // ---------------- work block: owns 64 rows ----------------
    int g   = bid - TBLK;
    int b   = g >> 4;                    // batch
    int blk = g & 15;                    // block within batch
    int rowbase = b * L + blk * ROWS_PB; // global first row
    int base4   = (rowbase * V) >> 2;    // uint4 offset (exact: rowbase%4==0... rowbase*257 div by 4 since rowbase mult of 64)

    // streaming: read x slice (extract -> sxs), zero out slice
    uint4 z0 = make_uint4(0u, 0u, 0u, 0u);
    #pragma unroll
    for (int half = 0; half < 2; half++) {
        int o = base4 + half * 2048 + tid;
        uint4 v[8];
        #pragma unroll
        for (int k = 0; k < 8; k++) v[k] = x4[o + k * 256];      // MLP 8
        #pragma unroll
        for (int k = 0; k < 8; k++) out4[o + k * 256] = z0;
        #pragma unroll
        for (int k = 0; k < 8; k++) {
            uint4 vv = v[k];
            if (vv.x | vv.y | vv.z | vv.w) {
                unsigned a[4] = { vv.x, vv.y, vv.z, vv.w };
                int eb = (o + k * 256) * 4;
                #pragma unroll
                for (int j = 0; j < 4; j++) {
                    if (a[j] != 0u) {
                        int idx = eb + j;
                        int row = idx / V;               // magic-mul div
                        int col = idx - row * V;
                        int lr  = row - rowbase;         // 0..63
                        sxs[(lr & 15) * 4 + (lr >> 4)] = col;
                    }
                }
            }
        }
    }
    if (tid < RU4 - 4096) {                              // 16 ragged uint4
        int o = base4 + 4096 + tid;
        uint4 vv = x4[o];
        out4[o] = z0;
        if (vv.x | vv.y | vv.z | vv.w) {
            unsigned a[4] = { vv.x, vv.y, vv.z, vv.w };
            int eb = o * 4;
            #pragma unroll
            for (int j = 0; j < 4; j++) {
                if (a[j] != 0u) {
                    int idx = eb + j;
                    int row = idx / V;
                    int col = idx - row * V;
                    int lr  = row - rowbase;
                    sxs[(lr & 15) * 4 + (lr >> 4)] = col;
                }
            }
        }
    }

    // tables ready? (they run first; this wait is ~never exposed)
    if (tid == 0) {
        while (*(volatile int*)&g_tabdone < TBLK) __nanosleep(32);
    }
    __syncthreads();
    __threadfence();
    for (int i = tid; i < 514 * REP; i += 256)
        tabR[i] = g_tab[slot2state(i >> 3)];             // REP = 8
    __syncthreads();

    // ---- segment maps: 4 chains/thread + extras (states 256/257, t<8) ----
    int rep = tid & (REP - 1);
    int xst = 256 + (tid & 1);
    int xun = (tid >> 1) & 3;
    bool extra = (tid < 8);

    int slot[5];
    #pragma unroll
    for (int j = 0; j < 4; j++) slot[j] = tid + 1;       // state tid -> slot tid+1
    slot[4] = (xst == V) ? 0 : xst + 1;

    #pragma unroll
    for (int t = 0; t < SEGLEN; t++) {
        uint4 xv = *(const uint4*)&sxs[t * 4];           // broadcast LDS.128
        unsigned xs[4] = { xv.x, xv.y, xv.z, xv.w };
        #pragma unroll
        for (int j = 0; j < 4; j++) {
            unsigned e = tabR[slot[j] * REP + rep];
            unsigned z = xs[j] * (e & 511u) + (e >> 9);
            slot[j] = (int)(z & 255u) - (int)(z >> 8) + 258;
        }
        if (extra) {
            unsigned e = tabR[slot[4] * REP + rep];
            unsigned z = (unsigned)sxs[t * 4 + xun] * (e & 511u) + (e >> 9);
            slot[4] = (int)(z & 255u) - (int)(z >> 8) + 258;
        }
    }

    #pragma unroll
    for (int j = 0; j < 4; j++)
        segmapS[j * NST + tid] = (short)slot2state(slot[j]);
    if (extra)
        segmapS[xun * NST + xst] = (short)slot2state(slot[4]);
    __syncthreads();

    // ---- compose own 4 segmaps -> block-map, publish ----
    {
        int cur = segmapS[tid];
        #pragma unroll
        for (int u = 1; u < UNITS; u++) cur = segmapS[u * NST + cur];
        g_bmap[(size_t)g * NST + tid] = (short)cur;
        if (tid < 2) {
            int c2 = segmapS[256 + tid];
            #pragma unroll
            for (int u = 1; u < UNITS; u++) c2 = segmapS[u * NST + c2];
            g_bmap[(size_t)g * NST + 256 + tid] = (short)c2;
        }
    }
    __threadfence();
    __syncthreads();
    if (tid == 0) isLast = (atomicAdd(&g_done[b], 1) == BPB - 1);
    __syncthreads();

    // ---- last block of batch: stitch 16 block-maps in SMEM ----
    if (isLast) {
        __threadfence();                                 // acquire peers' bmaps
        const uint4* src = (const uint4*)(g_bmap + (size_t)(b * BPB) * NST);
        uint4* dst = (uint4*)bmapsS;
        dst[tid]       = src[tid];                       // 516 uint4 total
        dst[256 + tid] = src[256 + tid];
        if (tid < 4) dst[512 + tid] = src[512 + tid];
        __syncthreads();
        if (tid == 0) {
            int st = V;  // ZERO
            #pragma unroll
            for (int k = 0; k < BPB; k++) {
                g_entry[b * BPB + k] = st;
                st = bmapsS[k * NST + st];
            }
            __threadfence();
            g_go[b] = 1;                                 // release
        }
    }

    // ---- wait, then replay + scatter ----
    if (tid == 0) {
        while (g_go[b] == 0) __nanosleep(32);
    }
    __syncthreads();
    __threadfence();

    if (tid == 0) {
        int st = g_entry[b * BPB + blk];
        #pragma unroll
        for (int u = 0; u < UNITS; u++) {
            entryU[u] = st;
            st = segmapS[u * NST + st];
        }
    }
    __syncthreads();

    {
        int w = tid >> 5, lane = tid & 31;
        if (w < UNITS && lane == 0) {
            int ent = entryU[w];
            int sl  = (ent == V) ? 0 : ent + 1;
            float* orow = (float*)out4 + (size_t)(rowbase + w * SEGLEN) * V;
            #pragma unroll
            for (int t = 0; t < SEGLEN; t++) {
                unsigned e = tabR[sl * REP];
                unsigned z = (unsigned)sxs[t * 4 + w] * (e & 511u) + (e >> 9);
                sl = (int)(z & 255u) - (int)(z >> 8) + 258;
                if (sl != 0) {
                    int oi = (sl <= V) ? sl - 1 : sl - (V + 1);
                    orow[(size_t)t * V + oi] = 1.0f;
                }
            }
        }
    }
    __syncthreads();

    if (tid == 0) {                                      // self-reset for replay
        if (atomicAdd(&g_fin[b], 1) == BPB - 1) {
            g_done[b] = 0;
            g_fin[b]  = 0;
            g_go[b]   = 0;
        }
        if (atomicAdd(&g_allfin, 1) == WBLK - 1) {
            g_tabdone = 0;
            g_allfin  = 0;
        }
    }
}

// ---------------------------------------------------------------------------
extern "C" void kernel_launch(void* const* d_in, const int* in_sizes, int n_in,
                              void* d_out, int out_size) {
    const float* x   = (const float*)d_in[0];   // [B, L, V] f32
    const float* W   = (const float*)d_in[1];   // [V, 2V]   f32
    const float* bb  = (const float*)d_in[2];   // [2V]      f32
    const int*   inv = (const int*)  d_in[3];   // [V]       i32

    k_F<<<TBLK + WBLK, 256>>>(W, bb, inv, (const uint4*)x, (uint4*)d_out);
}